// round 6
// baseline (speedup 1.0000x reference)
#include <cuda_runtime.h>
#include <cuda_fp16.h>
#include <cstdint>

// Problem constants (fixed by the dataset)
#define KBITS 8
#define MDIM  1024   // in_features  (GEMM K)
#define NDIM  1024   // out_features
#define TROWS 8192   // B*S

// ---------------------------------------------------------------------------
// Device scratch
// ---------------------------------------------------------------------------
__device__ __half g_xh[TROWS * MDIM];   // 16 MB  fp16(x)
__device__ __half g_w[NDIM * MDIM];     //  2 MB  W^T fp16 [n][m] (k-contig)

__device__ __forceinline__ uint32_t smem_u32(const void* p) {
    uint32_t a;
    asm("{ .reg .u64 t; cvta.to.shared.u64 t, %1; cvt.u32.u64 %0, t; }" : "=r"(a) : "l"(p));
    return a;
}

// ---------------------------------------------------------------------------
// Prep 1: x -> fp16 (8 floats per thread)
// ---------------------------------------------------------------------------
__global__ __launch_bounds__(256)
void split_x_kernel(const float* __restrict__ x) {
    int idx = (blockIdx.x * 256 + threadIdx.x) * 8;
    float4 v0 = *reinterpret_cast<const float4*>(x + idx);
    float4 v1 = *reinterpret_cast<const float4*>(x + idx + 4);
    __half h[8];
    h[0] = __float2half_rn(v0.x); h[1] = __float2half_rn(v0.y);
    h[2] = __float2half_rn(v0.z); h[3] = __float2half_rn(v0.w);
    h[4] = __float2half_rn(v1.x); h[5] = __float2half_rn(v1.y);
    h[6] = __float2half_rn(v1.z); h[7] = __float2half_rn(v1.w);
    *reinterpret_cast<uint4*>(g_xh + idx) = *reinterpret_cast<uint4*>(h);
}

// ---------------------------------------------------------------------------
// Prep 2: fold binary*scale -> W, transpose to [n][m], cast fp16.
// ---------------------------------------------------------------------------
__global__ __launch_bounds__(256)
void fold_kernel(const float* __restrict__ binary,
                 const float* __restrict__ scale) {
    __shared__ float tile[32][33];
    const int n0 = blockIdx.x * 32;
    const int m0 = blockIdx.y * 32;
    const int tx = threadIdx.x;   // 0..31
    const int ty = threadIdx.y;   // 0..7

    float s[KBITS];
#pragma unroll
    for (int k = 0; k < KBITS; k++) s[k] = scale[k * NDIM + n0 + tx];

#pragma unroll
    for (int r = 0; r < 4; r++) {
        int m = m0 + ty + r * 8;
        float acc = 0.f;
#pragma unroll
        for (int k = 0; k < KBITS; k++)
            acc += binary[(size_t)k * MDIM * NDIM + (size_t)m * NDIM + n0 + tx] * s[k];
        tile[ty + r * 8][tx] = acc;
    }
    __syncthreads();
#pragma unroll
    for (int r = 0; r < 4; r++) {
        int n = n0 + ty + r * 8;
        int m = m0 + tx;
        g_w[(size_t)n * MDIM + m] = __float2half_rn(tile[tx][ty + r * 8]);
    }
}

// ---------------------------------------------------------------------------
// GEMM: out = xh @ W + bias  via mma.sync fp16 (fp32 accum)
// CTA 128x256, 8 warps (2x4 grid of 64x64 warp tiles), KC=64, 3-stage cp.async.
// SMEM rows are 128 B (64 fp16); swizzle: chunk ^= (row & 7).
// ---------------------------------------------------------------------------
#define BM 128
#define BN 256
#define KC 64
#define STAGES 3
#define A_TILE_B (BM * 128)                 // 16 KB
#define B_TILE_B (BN * 128)                 // 32 KB
#define STAGE_B  (A_TILE_B + B_TILE_B)      // 48 KB
#define SMEM_DYN (STAGES * STAGE_B + 128)   // ~144 KB

__device__ __forceinline__ void cp16(uint32_t saddr, const void* gaddr) {
    asm volatile("cp.async.cg.shared.global [%0], [%1], 16;"
                 :: "r"(saddr), "l"(gaddr) : "memory");
}
__device__ __forceinline__ void ldsm_x4(uint32_t* r, uint32_t addr) {
    asm volatile("ldmatrix.sync.aligned.m8n8.x4.shared.b16 {%0,%1,%2,%3}, [%4];"
                 : "=r"(r[0]), "=r"(r[1]), "=r"(r[2]), "=r"(r[3]) : "r"(addr));
}
__device__ __forceinline__ void mma_f16(float* d, const uint32_t* a, const uint32_t* b) {
    asm volatile("mma.sync.aligned.m16n8k16.row.col.f32.f16.f16.f32 "
                 "{%0,%1,%2,%3}, {%4,%5,%6,%7}, {%8,%9}, {%0,%1,%2,%3};"
                 : "+f"(d[0]), "+f"(d[1]), "+f"(d[2]), "+f"(d[3])
                 : "r"(a[0]), "r"(a[1]), "r"(a[2]), "r"(a[3]), "r"(b[0]), "r"(b[1]));
}

__global__ __launch_bounds__(256, 1)
void gemm_kernel(const float* __restrict__ bias, float* __restrict__ out) {
    extern __shared__ char smem_raw[];
    const uint32_t sbase = (smem_u32(smem_raw) + 127u) & ~127u;

    const int tid = threadIdx.x;
    const int wid = tid >> 5, lid = tid & 31;
    const int warp_m = wid & 1;    // 2 warps along M (64 each)
    const int warp_n = wid >> 1;   // 4 warps along N (64 each)
    const int bx = blockIdx.x, by = blockIdx.y;

    const char* gA = (const char*)(g_xh + (size_t)by * BM * MDIM);
    const char* gB = (const char*)(g_w  + (size_t)bx * BN * MDIM);

    // ldmatrix row bases
    int arow[4];
#pragma unroll
    for (int f = 0; f < 4; f++) arow[f] = warp_m * 64 + f * 16 + (lid & 15);
    const int a_hl = lid >> 4;                 // 0/1 : k8-half
    int brow[4];
#pragma unroll
    for (int u = 0; u < 4; u++)
        brow[u] = warp_n * 64 + u * 16 + ((lid >> 4) & 1) * 8 + (lid & 7);
    const int b_ch = (lid >> 3) & 1;           // 0/1 : k8-half

    float acc[4][8][4];
#pragma unroll
    for (int i = 0; i < 4; i++)
#pragma unroll
        for (int j = 0; j < 8; j++)
#pragma unroll
            for (int q = 0; q < 4; q++) acc[i][j][q] = 0.f;

    const int NCH = MDIM / KC;  // 16
    auto issue = [&](int stage, int k0) {
        uint32_t sb = sbase + stage * STAGE_B;
        // A: 1024 chunks of 16B -> 4 per thread
#pragma unroll
        for (int i = 0; i < 4; i++) {
            int id = tid + i * 256;
            int row = id >> 3, c = id & 7;
            cp16(sb + row * 128 + ((c ^ (row & 7)) << 4),
                 gA + (size_t)row * (MDIM * 2) + k0 * 2 + c * 16);
        }
        // B: 2048 chunks -> 8 per thread
#pragma unroll
        for (int i = 0; i < 8; i++) {
            int id = tid + i * 256;
            int row = id >> 3, c = id & 7;
            cp16(sb + A_TILE_B + row * 128 + ((c ^ (row & 7)) << 4),
                 gB + (size_t)row * (MDIM * 2) + k0 * 2 + c * 16);
        }
        asm volatile("cp.async.commit_group;" ::: "memory");
    };

    issue(0, 0);
    issue(1, KC);

    for (int c = 0; c < NCH; c++) {
        asm volatile("cp.async.wait_group 1;" ::: "memory");
        __syncthreads();
        if (c + 2 < NCH) issue((c + 2) % STAGES, (c + 2) * KC);

        const uint32_t sA = sbase + (c % STAGES) * STAGE_B;
        const uint32_t sB = sA + A_TILE_B;
#pragma unroll
        for (int ks = 0; ks < 4; ks++) {
            uint32_t a[4][4], b[4][4];
#pragma unroll
            for (int f = 0; f < 4; f++)
                ldsm_x4(a[f], sA + arow[f] * 128 +
                              (((ks * 2 + a_hl) ^ (arow[f] & 7)) << 4));
#pragma unroll
            for (int u = 0; u < 4; u++)
                ldsm_x4(b[u], sB + brow[u] * 128 +
                              (((ks * 2 + b_ch) ^ (brow[u] & 7)) << 4));
#pragma unroll
            for (int i = 0; i < 4; i++)
#pragma unroll
                for (int j = 0; j < 8; j++)
                    mma_f16(acc[i][j], a[i], &b[j >> 1][(j & 1) * 2]);
        }
    }

    // ---- epilogue: bias + store ----
    const int row0 = by * BM + warp_m * 64;
    const int col0 = bx * BN + warp_n * 64;
    const int lrow = lid >> 2;
    const int lcol = (lid & 3) * 2;
#pragma unroll
    for (int j = 0; j < 8; j++) {
        int c0 = col0 + j * 8 + lcol;
        float2 bv = *reinterpret_cast<const float2*>(bias + c0);
#pragma unroll
        for (int i = 0; i < 4; i++) {
            int r = row0 + i * 16 + lrow;
            float2 o0 = {acc[i][j][0] + bv.x, acc[i][j][1] + bv.y};
            float2 o1 = {acc[i][j][2] + bv.x, acc[i][j][3] + bv.y};
            *reinterpret_cast<float2*>(out + (size_t)r * NDIM + c0) = o0;
            *reinterpret_cast<float2*>(out + (size_t)(r + 8) * NDIM + c0) = o1;
        }
    }
}

// ---------------------------------------------------------------------------
// Launch: fork prep kernels onto two streams (capture-safe event fork/join),
// then the GEMM after both complete.
// ---------------------------------------------------------------------------
extern "C" void kernel_launch(void* const* d_in, const int* in_sizes, int n_in,
                              void* d_out, int out_size) {
    const float* x      = (const float*)d_in[0];  // [4,2048,1024]
    const float* binary = (const float*)d_in[1];  // [8,1024,1024]
    const float* scale  = (const float*)d_in[2];  // [8,1,1024]
    const float* bias   = (const float*)d_in[3];  // [1024]
    float* out = (float*)d_out;

    static cudaStream_t s2 = nullptr;
    static cudaEvent_t evFork = nullptr, evJoin = nullptr;
    static int init = 0;
    if (!init) {
        cudaStreamCreateWithFlags(&s2, cudaStreamNonBlocking);
        cudaEventCreateWithFlags(&evFork, cudaEventDisableTiming);
        cudaEventCreateWithFlags(&evJoin, cudaEventDisableTiming);
        cudaFuncSetAttribute(gemm_kernel, cudaFuncAttributeMaxDynamicSharedMemorySize, SMEM_DYN);
        init = 1;
    }

    // fork: fold on side stream, split on main stream
    cudaEventRecord(evFork, 0);
    cudaStreamWaitEvent(s2, evFork, 0);
    fold_kernel<<<dim3(NDIM / 32, MDIM / 32), dim3(32, 8), 0, s2>>>(binary, scale);
    split_x_kernel<<<(TROWS * MDIM) / 8 / 256, 256>>>(x);
    // join
    cudaEventRecord(evJoin, s2);
    cudaStreamWaitEvent(0, evJoin, 0);

    gemm_kernel<<<dim3(NDIM / BN, TROWS / BM), 256, SMEM_DYN>>>(bias, out);
}

// round 7
// speedup vs baseline: 1.0371x; 1.0371x over previous
#include <cuda_runtime.h>
#include <cuda_fp16.h>
#include <cstdint>

// Problem constants (fixed by the dataset)
#define KBITS 8
#define MDIM  1024   // in_features  (GEMM K)
#define NDIM  1024   // out_features
#define TROWS 8192   // B*S

// ---------------------------------------------------------------------------
// Device scratch
// ---------------------------------------------------------------------------
__device__ __half g_xh[TROWS * MDIM];   // 16 MB  fp16(x)
__device__ __half g_w[NDIM * MDIM];     //  2 MB  W^T fp16 [n][m] (k-contig)

__device__ __forceinline__ uint32_t smem_u32(const void* p) {
    uint32_t a;
    asm("{ .reg .u64 t; cvta.to.shared.u64 t, %1; cvt.u32.u64 %0, t; }" : "=r"(a) : "l"(p));
    return a;
}

// ---------------------------------------------------------------------------
// Prep 1: x -> fp16 (16 floats per thread for higher MLP)
// ---------------------------------------------------------------------------
__global__ __launch_bounds__(256)
void split_x_kernel(const float* __restrict__ x) {
    int idx = (blockIdx.x * 256 + threadIdx.x) * 16;
#pragma unroll
    for (int half = 0; half < 2; half++) {
        int o = idx + half * 8;
        float4 v0 = *reinterpret_cast<const float4*>(x + o);
        float4 v1 = *reinterpret_cast<const float4*>(x + o + 4);
        __half h[8];
        h[0] = __float2half_rn(v0.x); h[1] = __float2half_rn(v0.y);
        h[2] = __float2half_rn(v0.z); h[3] = __float2half_rn(v0.w);
        h[4] = __float2half_rn(v1.x); h[5] = __float2half_rn(v1.y);
        h[6] = __float2half_rn(v1.z); h[7] = __float2half_rn(v1.w);
        *reinterpret_cast<uint4*>(g_xh + o) = *reinterpret_cast<uint4*>(h);
    }
}

// ---------------------------------------------------------------------------
// Prep 2: fold binary*scale -> W, transpose to [n][m], cast fp16.
// ---------------------------------------------------------------------------
__global__ __launch_bounds__(256)
void fold_kernel(const float* __restrict__ binary,
                 const float* __restrict__ scale) {
    __shared__ float tile[32][33];
    const int n0 = blockIdx.x * 32;
    const int m0 = blockIdx.y * 32;
    const int tx = threadIdx.x;   // 0..31
    const int ty = threadIdx.y;   // 0..7

    float s[KBITS];
#pragma unroll
    for (int k = 0; k < KBITS; k++) s[k] = scale[k * NDIM + n0 + tx];

#pragma unroll
    for (int r = 0; r < 4; r++) {
        int m = m0 + ty + r * 8;
        float acc = 0.f;
#pragma unroll
        for (int k = 0; k < KBITS; k++)
            acc += binary[(size_t)k * MDIM * NDIM + (size_t)m * NDIM + n0 + tx] * s[k];
        tile[ty + r * 8][tx] = acc;
    }
    __syncthreads();
#pragma unroll
    for (int r = 0; r < 4; r++) {
        int n = n0 + ty + r * 8;
        int m = m0 + tx;
        g_w[(size_t)n * MDIM + m] = __float2half_rn(tile[tx][ty + r * 8]);
    }
}

// ---------------------------------------------------------------------------
// GEMM: out = xh @ W + bias  via mma.sync fp16 (fp32 accum)
// CTA 128x128, 4 warps (2x2 grid of 64x64 warp tiles), 128 threads,
// KC=64, 3-stage cp.async pipeline, 2 CTAs/SM.
// SMEM rows are 128 B (64 fp16); swizzle: chunk ^= (row & 7).
// ---------------------------------------------------------------------------
#define BM 128
#define BN 128
#define KC 64
#define STAGES 3
#define TILE_B   (128 * 128)           // one operand tile: 16 KB
#define STAGE_B  (2 * TILE_B)          // A + B = 32 KB
#define SMEM_DYN (STAGES * STAGE_B + 128)

__device__ __forceinline__ void cp16(uint32_t saddr, const void* gaddr) {
    asm volatile("cp.async.cg.shared.global [%0], [%1], 16;"
                 :: "r"(saddr), "l"(gaddr) : "memory");
}
__device__ __forceinline__ void ldsm_x4(uint32_t* r, uint32_t addr) {
    asm volatile("ldmatrix.sync.aligned.m8n8.x4.shared.b16 {%0,%1,%2,%3}, [%4];"
                 : "=r"(r[0]), "=r"(r[1]), "=r"(r[2]), "=r"(r[3]) : "r"(addr));
}
__device__ __forceinline__ void mma_f16(float* d, const uint32_t* a, const uint32_t* b) {
    asm volatile("mma.sync.aligned.m16n8k16.row.col.f32.f16.f16.f32 "
                 "{%0,%1,%2,%3}, {%4,%5,%6,%7}, {%8,%9}, {%0,%1,%2,%3};"
                 : "+f"(d[0]), "+f"(d[1]), "+f"(d[2]), "+f"(d[3])
                 : "r"(a[0]), "r"(a[1]), "r"(a[2]), "r"(a[3]), "r"(b[0]), "r"(b[1]));
}

__global__ __launch_bounds__(128, 2)
void gemm_kernel(const float* __restrict__ bias, float* __restrict__ out) {
    extern __shared__ char smem_raw[];
    const uint32_t sbase = (smem_u32(smem_raw) + 127u) & ~127u;

    const int tid = threadIdx.x;
    const int wid = tid >> 5, lid = tid & 31;
    const int warp_m = wid & 1;    // 2 warps along M (64 each)
    const int warp_n = wid >> 1;   // 2 warps along N (64 each)
    const int bx = blockIdx.x, by = blockIdx.y;

    const char* gA = (const char*)(g_xh + (size_t)by * BM * MDIM);
    const char* gB = (const char*)(g_w  + (size_t)bx * BN * MDIM);

    // ldmatrix row bases
    int arow[4];
#pragma unroll
    for (int f = 0; f < 4; f++) arow[f] = warp_m * 64 + f * 16 + (lid & 15);
    const int a_hl = lid >> 4;                 // 0/1 : k8-half
    int brow[4];
#pragma unroll
    for (int u = 0; u < 4; u++)
        brow[u] = warp_n * 64 + u * 16 + ((lid >> 4) & 1) * 8 + (lid & 7);
    const int b_ch = (lid >> 3) & 1;           // 0/1 : k8-half

    float acc[4][8][4];
#pragma unroll
    for (int i = 0; i < 4; i++)
#pragma unroll
        for (int j = 0; j < 8; j++)
#pragma unroll
            for (int q = 0; q < 4; q++) acc[i][j][q] = 0.f;

    const int NCH = MDIM / KC;  // 16
    auto issue = [&](int stage, int k0) {
        uint32_t sb = sbase + stage * STAGE_B;
        // A: 1024 chunks of 16B -> 8 per thread (128 threads)
#pragma unroll
        for (int i = 0; i < 8; i++) {
            int id = tid + i * 128;
            int row = id >> 3, c = id & 7;
            size_t src = (size_t)row * (MDIM * 2) + k0 * 2 + c * 16;
            uint32_t dst = row * 128 + ((c ^ (row & 7)) << 4);
            cp16(sb + dst, gA + src);
            cp16(sb + TILE_B + dst, gB + src);
        }
        asm volatile("cp.async.commit_group;" ::: "memory");
    };

    issue(0, 0);
    issue(1, KC);

    for (int c = 0; c < NCH; c++) {
        asm volatile("cp.async.wait_group 1;" ::: "memory");
        __syncthreads();
        if (c + 2 < NCH) issue((c + 2) % STAGES, (c + 2) * KC);

        const uint32_t sA = sbase + (c % STAGES) * STAGE_B;
        const uint32_t sB = sA + TILE_B;
#pragma unroll
        for (int ks = 0; ks < 4; ks++) {
            uint32_t a[4][4], b[4][4];
#pragma unroll
            for (int f = 0; f < 4; f++)
                ldsm_x4(a[f], sA + arow[f] * 128 +
                              (((ks * 2 + a_hl) ^ (arow[f] & 7)) << 4));
#pragma unroll
            for (int u = 0; u < 4; u++)
                ldsm_x4(b[u], sB + brow[u] * 128 +
                              (((ks * 2 + b_ch) ^ (brow[u] & 7)) << 4));
#pragma unroll
            for (int i = 0; i < 4; i++)
#pragma unroll
                for (int j = 0; j < 8; j++)
                    mma_f16(acc[i][j], a[i], &b[j >> 1][(j & 1) * 2]);
        }
    }

    // ---- epilogue: bias + store ----
    const int row0 = by * BM + warp_m * 64;
    const int col0 = bx * BN + warp_n * 64;
    const int lrow = lid >> 2;
    const int lcol = (lid & 3) * 2;
#pragma unroll
    for (int j = 0; j < 8; j++) {
        int c0 = col0 + j * 8 + lcol;
        float2 bv = *reinterpret_cast<const float2*>(bias + c0);
#pragma unroll
        for (int i = 0; i < 4; i++) {
            int r = row0 + i * 16 + lrow;
            float2 o0 = {acc[i][j][0] + bv.x, acc[i][j][1] + bv.y};
            float2 o1 = {acc[i][j][2] + bv.x, acc[i][j][3] + bv.y};
            *reinterpret_cast<float2*>(out + (size_t)r * NDIM + c0) = o0;
            *reinterpret_cast<float2*>(out + (size_t)(r + 8) * NDIM + c0) = o1;
        }
    }
}

// ---------------------------------------------------------------------------
// Launch: prep forked onto two streams, GEMM after join.
// ---------------------------------------------------------------------------
extern "C" void kernel_launch(void* const* d_in, const int* in_sizes, int n_in,
                              void* d_out, int out_size) {
    const float* x      = (const float*)d_in[0];  // [4,2048,1024]
    const float* binary = (const float*)d_in[1];  // [8,1024,1024]
    const float* scale  = (const float*)d_in[2];  // [8,1,1024]
    const float* bias   = (const float*)d_in[3];  // [1024]
    float* out = (float*)d_out;

    static cudaStream_t s2 = nullptr;
    static cudaEvent_t evFork = nullptr, evJoin = nullptr;
    static int init = 0;
    if (!init) {
        cudaStreamCreateWithFlags(&s2, cudaStreamNonBlocking);
        cudaEventCreateWithFlags(&evFork, cudaEventDisableTiming);
        cudaEventCreateWithFlags(&evJoin, cudaEventDisableTiming);
        cudaFuncSetAttribute(gemm_kernel, cudaFuncAttributeMaxDynamicSharedMemorySize, SMEM_DYN);
        init = 1;
    }

    // fork: fold on side stream, split on main stream
    cudaEventRecord(evFork, 0);
    cudaStreamWaitEvent(s2, evFork, 0);
    fold_kernel<<<dim3(NDIM / 32, MDIM / 32), dim3(32, 8), 0, s2>>>(binary, scale);
    split_x_kernel<<<(TROWS * MDIM) / 16 / 256, 256>>>(x);
    // join
    cudaEventRecord(evJoin, s2);
    cudaStreamWaitEvent(0, evJoin, 0);

    gemm_kernel<<<dim3(NDIM / BN, TROWS / BM), 128, SMEM_DYN>>>(bias, out);
}